// round 10
// baseline (speedup 1.0000x reference)
#include <cuda_runtime.h>
#include <cuda_fp16.h>

#define N_MAX 100000
#define E_MAX 1200000
#define DIN   64
#define DHID  64
#define DOUT  34
#define SCAN_BS 512
#define NB_MAX ((N_MAX + SCAN_BS - 1) / SCAN_BS)

// ---- scratch (allocation-free: __device__ globals) ----
__device__ int    g_deg [N_MAX];
__device__ float  g_dinv[N_MAX];
__device__ int    g_off [N_MAX + 1];
__device__ int    g_cur [N_MAX];
__device__ int    g_bsum[NB_MAX];
__device__ int    g_esrc[E_MAX];
__device__ __half g_xh [(size_t)N_MAX * DIN];   // dinv*x, fp16 gather table
__device__ __half g_sh [(size_t)N_MAX * DIN];   // aggregated input, fp16 (GEMM1 A)
__device__ __half g_hwh[(size_t)N_MAX * DOUT];  // dinv*hw, fp16 gather table

// ---------------------------------------------------------------------------
__global__ void k_deg_count(const int* __restrict__ dst, int e) {
    int i0 = (blockIdx.x * blockDim.x + threadIdx.x) * 4;
    if (i0 + 3 < e) {
        int d0 = dst[i0], d1 = dst[i0 + 1], d2 = dst[i0 + 2], d3 = dst[i0 + 3];
        atomicAdd(&g_deg[d0], 1);
        atomicAdd(&g_deg[d1], 1);
        atomicAdd(&g_deg[d2], 1);
        atomicAdd(&g_deg[d3], 1);
    } else {
        for (int i = i0; i < e; i++) atomicAdd(&g_deg[dst[i]], 1);
    }
}

__global__ void k_scan1(int n) {
    __shared__ int sh[SCAN_BS];
    int i = blockIdx.x * SCAN_BS + threadIdx.x;
    int v = (i < n) ? g_deg[i] : 0;
    if (i < n) g_dinv[i] = rsqrtf((float)(v + 1));
    sh[threadIdx.x] = v;
    __syncthreads();
    for (int off = 1; off < SCAN_BS; off <<= 1) {
        int t = (threadIdx.x >= off) ? sh[threadIdx.x - off] : 0;
        __syncthreads();
        sh[threadIdx.x] += t;
        __syncthreads();
    }
    if (i < n) g_off[i] = sh[threadIdx.x] - v;
    if (threadIdx.x == SCAN_BS - 1) g_bsum[blockIdx.x] = sh[threadIdx.x];
}

__global__ void k_scan3(int nb, int n) {
    __shared__ int red[SCAN_BS / 32];
    __shared__ int pref;
    int sb = blockIdx.x, t = threadIdx.x;
    int v = (t < sb) ? g_bsum[t] : 0;
#pragma unroll
    for (int o = 16; o; o >>= 1) v += __shfl_xor_sync(0xffffffffu, v, o);
    if ((t & 31) == 0) red[t >> 5] = v;
    __syncthreads();
    if (t < 32) {
        int vv = (t < SCAN_BS / 32) ? red[t] : 0;
#pragma unroll
        for (int o = 16; o; o >>= 1) vv += __shfl_xor_sync(0xffffffffu, vv, o);
        if (t == 0) pref = vv;
    }
    __syncthreads();
    int prefix = pref;
    int i = sb * SCAN_BS + t;
    if (i < n) {
        int o = g_off[i] + prefix;
        g_off[i] = o;
        g_cur[i] = o;
    }
    if (sb == nb - 1 && t == 0) g_off[n] = prefix + g_bsum[sb];
}

__global__ void k_x2h(const float* __restrict__ x, int n) {
    int tid = blockIdx.x * blockDim.x + threadIdx.x;
    int row = tid >> 4, sub = tid & 15;
    if (row >= n) return;
    float dn = g_dinv[row];
    float4 v = *(const float4*)(x + (size_t)row * DIN + sub * 4);
    __half2 h01 = __floats2half2_rn(v.x * dn, v.y * dn);
    __half2 h23 = __floats2half2_rn(v.z * dn, v.w * dn);
    uint2 raw;
    raw.x = *(unsigned*)&h01;
    raw.y = *(unsigned*)&h23;
    *(uint2*)(g_xh + (size_t)row * DIN + sub * 4) = raw;
}

__global__ void k_fill(const int* __restrict__ src, const int* __restrict__ dst, int e) {
    int i0 = (blockIdx.x * blockDim.x + threadIdx.x) * 4;
    if (i0 + 3 < e) {
        int s0 = src[i0], s1 = src[i0 + 1], s2 = src[i0 + 2], s3 = src[i0 + 3];
        int d0 = dst[i0], d1 = dst[i0 + 1], d2 = dst[i0 + 2], d3 = dst[i0 + 3];
        int p0 = atomicAdd(&g_cur[d0], 1);
        int p1 = atomicAdd(&g_cur[d1], 1);
        int p2 = atomicAdd(&g_cur[d2], 1);
        int p3 = atomicAdd(&g_cur[d3], 1);
        g_esrc[p0] = s0; g_esrc[p1] = s1; g_esrc[p2] = s2; g_esrc[p3] = s3;
    } else {
        for (int i = i0; i < e; i++) {
            int pos = atomicAdd(&g_cur[dst[i]], 1);
            g_esrc[pos] = src[i];
        }
    }
}

// ---------------------------------------------------------------------------
// Pre-GEMM aggregation: quarter-warp streams. 8 lanes x uint4(16B) = 128B row;
// warp = 4 independent edge streams x unroll-2 -> 8 LDG.128 in flight,
// ~6 warp-instrs/edge. Cross-stream combine via shfl_xor(8,16) at node end.
__global__ void k_aggx(const float* __restrict__ x, int n) {
    int warp = threadIdx.x >> 5, lane = threadIdx.x & 31;
    int node = blockIdx.x * 8 + warp;
    if (node >= n) return;
    int beg = g_off[node], end = g_off[node + 1];
    int q = lane >> 3, sub = lane & 7;

    float acc[8];
#pragma unroll
    for (int i = 0; i < 8; i++) acc[i] = 0.f;

    for (int j = beg; j < end; j += 32) {
        int idx = j + lane;
        int ed = (idx < end) ? g_esrc[idx] : 0;
        int m  = min(32, end - j);
        int mt = (m + 3) >> 2;       // trips per quarter-stream (warp-uniform)
        int t  = 0;
        for (; t + 2 <= mt; t += 2) {
            int l0 = 4 * t + q, l1 = l0 + 4;
            int s0 = __shfl_sync(0xffffffffu, ed, l0);
            int s1 = __shfl_sync(0xffffffffu, ed, l1);
            if (l0 < m) {
                uint4 raw = *(const uint4*)(g_xh + (size_t)s0 * DIN + sub * 8);
                float2 f;
                f = __half22float2(*(__half2*)&raw.x); acc[0] += f.x; acc[1] += f.y;
                f = __half22float2(*(__half2*)&raw.y); acc[2] += f.x; acc[3] += f.y;
                f = __half22float2(*(__half2*)&raw.z); acc[4] += f.x; acc[5] += f.y;
                f = __half22float2(*(__half2*)&raw.w); acc[6] += f.x; acc[7] += f.y;
            }
            if (l1 < m) {
                uint4 raw = *(const uint4*)(g_xh + (size_t)s1 * DIN + sub * 8);
                float2 f;
                f = __half22float2(*(__half2*)&raw.x); acc[0] += f.x; acc[1] += f.y;
                f = __half22float2(*(__half2*)&raw.y); acc[2] += f.x; acc[3] += f.y;
                f = __half22float2(*(__half2*)&raw.z); acc[4] += f.x; acc[5] += f.y;
                f = __half22float2(*(__half2*)&raw.w); acc[6] += f.x; acc[7] += f.y;
            }
        }
        for (; t < mt; t++) {
            int l0 = 4 * t + q;
            int s0 = __shfl_sync(0xffffffffu, ed, l0);
            if (l0 < m) {
                uint4 raw = *(const uint4*)(g_xh + (size_t)s0 * DIN + sub * 8);
                float2 f;
                f = __half22float2(*(__half2*)&raw.x); acc[0] += f.x; acc[1] += f.y;
                f = __half22float2(*(__half2*)&raw.y); acc[2] += f.x; acc[3] += f.y;
                f = __half22float2(*(__half2*)&raw.z); acc[4] += f.x; acc[5] += f.y;
                f = __half22float2(*(__half2*)&raw.w); acc[6] += f.x; acc[7] += f.y;
            }
        }
    }
    // combine the 4 quarter-streams (lanes with equal sub)
#pragma unroll
    for (int i = 0; i < 8; i++) {
        acc[i] += __shfl_xor_sync(0xffffffffu, acc[i], 8);
        acc[i] += __shfl_xor_sync(0xffffffffu, acc[i], 16);
    }
    if (q == 0) {
        float dn = g_dinv[node];
        const float4* xp = (const float4*)(x + (size_t)node * DIN + sub * 8);
        float4 xa = xp[0], xb = xp[1];
        float s0 = fmaf(dn, acc[0], dn * dn * xa.x);
        float s1 = fmaf(dn, acc[1], dn * dn * xa.y);
        float s2 = fmaf(dn, acc[2], dn * dn * xa.z);
        float s3 = fmaf(dn, acc[3], dn * dn * xa.w);
        float s4 = fmaf(dn, acc[4], dn * dn * xb.x);
        float s5 = fmaf(dn, acc[5], dn * dn * xb.y);
        float s6 = fmaf(dn, acc[6], dn * dn * xb.z);
        float s7 = fmaf(dn, acc[7], dn * dn * xb.w);
        __half2 h0 = __floats2half2_rn(s0, s1);
        __half2 h1 = __floats2half2_rn(s2, s3);
        __half2 h2 = __floats2half2_rn(s4, s5);
        __half2 h3 = __floats2half2_rn(s6, s7);
        uint4 raw;
        raw.x = *(unsigned*)&h0; raw.y = *(unsigned*)&h1;
        raw.z = *(unsigned*)&h2; raw.w = *(unsigned*)&h3;
        *(uint4*)(g_sh + (size_t)node * DIN + sub * 8) = raw;
    }
}

// ---------------------------------------------------------------------------
// Tensor-core fused kernel (proven round-9 config, unchanged).
__device__ __forceinline__ void mma16816(float& c0, float& c1, float& c2, float& c3,
                                         unsigned a0, unsigned a1, unsigned a2, unsigned a3,
                                         unsigned b0, unsigned b1) {
    asm volatile(
        "mma.sync.aligned.m16n8k16.row.col.f32.f16.f16.f32 "
        "{%0,%1,%2,%3}, {%4,%5,%6,%7}, {%8,%9}, {%0,%1,%2,%3};"
        : "+f"(c0), "+f"(c1), "+f"(c2), "+f"(c3)
        : "r"(a0), "r"(a1), "r"(a2), "r"(a3), "r"(b0), "r"(b1));
}

__global__ void __launch_bounds__(256) k_fused(
        const float* __restrict__ W1, const float* __restrict__ b1,
        const float* __restrict__ W2, const float* __restrict__ b2,
        float* __restrict__ out, int n) {
    __shared__ __half W1t[64][72];
    __shared__ __half W2t[40][72];
    __shared__ float  b1s[64];
    int tid = threadIdx.x;
    for (int i = tid; i < 64 * 64; i += 256) {
        int k = i >> 6, nn = i & 63;
        W1t[nn][k] = __float2half(W1[k * DHID + nn]);
    }
    for (int i = tid; i < 40 * 64; i += 256) {
        int nn = i / 64, k = i - nn * 64;
        W2t[nn][k] = (nn < DOUT) ? __float2half(W2[k * DOUT + nn]) : __float2half(0.f);
    }
    if (tid < 64) b1s[tid] = b1[tid];
    __syncthreads();

    int warp = tid >> 5, lane = tid & 31;
    int qr = lane >> 2, qc = lane & 3;
    int row0 = blockIdx.x * 128 + warp * 16;
    int r1 = row0 + qr, r2 = r1 + 8;
    bool v1 = r1 < n, v2 = r2 < n;

    const unsigned* gs32 = (const unsigned*)g_sh;

    float c[8][4];
#pragma unroll
    for (int nt = 0; nt < 8; nt++)
        c[nt][0] = c[nt][1] = c[nt][2] = c[nt][3] = 0.f;

#pragma unroll
    for (int kt = 0; kt < 4; kt++) {
        int col = kt * 16 + qc * 2;
        unsigned a0 = 0, a1 = 0, a2 = 0, a3 = 0;
        if (v1) { a0 = gs32[(r1 * DIN + col) >> 1]; a2 = gs32[(r1 * DIN + col + 8) >> 1]; }
        if (v2) { a1 = gs32[(r2 * DIN + col) >> 1]; a3 = gs32[(r2 * DIN + col + 8) >> 1]; }
#pragma unroll
        for (int nt = 0; nt < 8; nt++) {
            unsigned b0 = *(const unsigned*)&W1t[nt * 8 + qr][col];
            unsigned b1r = *(const unsigned*)&W1t[nt * 8 + qr][col + 8];
            mma16816(c[nt][0], c[nt][1], c[nt][2], c[nt][3], a0, a1, a2, a3, b0, b1r);
        }
    }

    float m1 = 0.f, m2 = 0.f;
#pragma unroll
    for (int nt = 0; nt < 8; nt++) {
        float2 bb = *(const float2*)&b1s[nt * 8 + qc * 2];
        c[nt][0] = fmaxf(c[nt][0] + bb.x, 0.f);
        c[nt][1] = fmaxf(c[nt][1] + bb.y, 0.f);
        c[nt][2] = fmaxf(c[nt][2] + bb.x, 0.f);
        c[nt][3] = fmaxf(c[nt][3] + bb.y, 0.f);
        m1 = fmaxf(m1, fmaxf(c[nt][0], c[nt][1]));
        m2 = fmaxf(m2, fmaxf(c[nt][2], c[nt][3]));
    }
    m1 = fmaxf(m1, __shfl_xor_sync(0xffffffffu, m1, 1));
    m1 = fmaxf(m1, __shfl_xor_sync(0xffffffffu, m1, 2));
    m2 = fmaxf(m2, __shfl_xor_sync(0xffffffffu, m2, 1));
    m2 = fmaxf(m2, __shfl_xor_sync(0xffffffffu, m2, 2));
    float s1 = 0.f, s2 = 0.f;
#pragma unroll
    for (int nt = 0; nt < 8; nt++) {
        c[nt][0] = __expf(c[nt][0] - m1);
        c[nt][1] = __expf(c[nt][1] - m1);
        c[nt][2] = __expf(c[nt][2] - m2);
        c[nt][3] = __expf(c[nt][3] - m2);
        s1 += c[nt][0] + c[nt][1];
        s2 += c[nt][2] + c[nt][3];
    }
    s1 += __shfl_xor_sync(0xffffffffu, s1, 1);
    s1 += __shfl_xor_sync(0xffffffffu, s1, 2);
    s2 += __shfl_xor_sync(0xffffffffu, s2, 1);
    s2 += __shfl_xor_sync(0xffffffffu, s2, 2);
    float i1 = 1.0f / s1, i2 = 1.0f / s2;

    unsigned pa[4][4];
#pragma unroll
    for (int kt = 0; kt < 4; kt++) {
        __half2 h;
        h = __floats2half2_rn(c[2 * kt][0] * i1, c[2 * kt][1] * i1);         pa[kt][0] = *(unsigned*)&h;
        h = __floats2half2_rn(c[2 * kt][2] * i2, c[2 * kt][3] * i2);         pa[kt][1] = *(unsigned*)&h;
        h = __floats2half2_rn(c[2 * kt + 1][0] * i1, c[2 * kt + 1][1] * i1); pa[kt][2] = *(unsigned*)&h;
        h = __floats2half2_rn(c[2 * kt + 1][2] * i2, c[2 * kt + 1][3] * i2); pa[kt][3] = *(unsigned*)&h;
    }

    float dn1 = v1 ? g_dinv[r1] : 0.f;
    float dn2 = v2 ? g_dinv[r2] : 0.f;

#pragma unroll
    for (int nt = 0; nt < 5; nt++) {
        float d0 = 0.f, d1 = 0.f, d2 = 0.f, d3 = 0.f;
#pragma unroll
        for (int kt = 0; kt < 4; kt++) {
            int kk = kt * 16 + qc * 2;
            unsigned b0 = *(const unsigned*)&W2t[nt * 8 + qr][kk];
            unsigned b1r = *(const unsigned*)&W2t[nt * 8 + qr][kk + 8];
            mma16816(d0, d1, d2, d3, pa[kt][0], pa[kt][1], pa[kt][2], pa[kt][3], b0, b1r);
        }
        int col = nt * 8 + qc * 2;
        if (col + 1 < DOUT) {
            float2 bb = *(const float2*)&b2[col];
            if (v1) {
                float2 o;
                o.x = fmaf(dn1 * dn1, d0, bb.x);
                o.y = fmaf(dn1 * dn1, d1, bb.y);
                *(float2*)&out[(size_t)r1 * DOUT + col] = o;
                __half2 hh = __floats2half2_rn(dn1 * d0, dn1 * d1);
                *(__half2*)&g_hwh[(size_t)r1 * DOUT + col] = hh;
            }
            if (v2) {
                float2 o;
                o.x = fmaf(dn2 * dn2, d2, bb.x);
                o.y = fmaf(dn2 * dn2, d3, bb.y);
                *(float2*)&out[(size_t)r2 * DOUT + col] = o;
                __half2 hh = __floats2half2_rn(dn2 * d2, dn2 * d3);
                *(__half2*)&g_hwh[(size_t)r2 * DOUT + col] = hh;
            }
        }
    }
}

// ---------------------------------------------------------------------------
// Layer-2 aggregation (proven config, unchanged).
__global__ void k_agg2(float* __restrict__ out, int n) {
    int warp = threadIdx.x >> 5, lane = threadIdx.x & 31;
    int node = blockIdx.x * 8 + warp;
    if (node >= n) return;
    int beg = g_off[node], end = g_off[node + 1];
    int half = lane >> 4, sub = lane & 15;

    float2 acc  = make_float2(0.f, 0.f);
    float2 accx = make_float2(0.f, 0.f);
    for (int j = beg; j < end; j += 32) {
        int idx = j + lane;
        int ed = (idx < end) ? g_esrc[idx] : 0;
        int m  = min(32, end - j);
        int mt = (m + 1) >> 1;
        int t  = 0;
        for (; t + 2 <= mt; t += 2) {
            int l0 = 2 * t + half, l1 = l0 + 2;
            int s0 = __shfl_sync(0xffffffffu, ed, l0);
            int s1 = __shfl_sync(0xffffffffu, ed, l1);
            if (l0 < m) {
                const __half* hp = g_hwh + (size_t)s0 * DOUT;
                float2 v = __half22float2(*(const __half2*)(hp + sub * 2));
                acc.x += v.x; acc.y += v.y;
                if (sub == 0) {
                    float2 u = __half22float2(*(const __half2*)(hp + 32));
                    accx.x += u.x; accx.y += u.y;
                }
            }
            if (l1 < m) {
                const __half* hp = g_hwh + (size_t)s1 * DOUT;
                float2 v = __half22float2(*(const __half2*)(hp + sub * 2));
                acc.x += v.x; acc.y += v.y;
                if (sub == 0) {
                    float2 u = __half22float2(*(const __half2*)(hp + 32));
                    accx.x += u.x; accx.y += u.y;
                }
            }
        }
        for (; t < mt; t++) {
            int l0 = 2 * t + half;
            int s0 = __shfl_sync(0xffffffffu, ed, l0);
            if (l0 < m) {
                const __half* hp = g_hwh + (size_t)s0 * DOUT;
                float2 v = __half22float2(*(const __half2*)(hp + sub * 2));
                acc.x += v.x; acc.y += v.y;
                if (sub == 0) {
                    float2 u = __half22float2(*(const __half2*)(hp + 32));
                    accx.x += u.x; accx.y += u.y;
                }
            }
        }
    }
    acc.x  += __shfl_xor_sync(0xffffffffu, acc.x,  16);
    acc.y  += __shfl_xor_sync(0xffffffffu, acc.y,  16);
    accx.x += __shfl_xor_sync(0xffffffffu, accx.x, 16);
    accx.y += __shfl_xor_sync(0xffffffffu, accx.y, 16);
    if (half == 0) {
        float dn = g_dinv[node];
        size_t oo = (size_t)node * DOUT;
        out[oo + sub * 2]     = fmaf(dn, acc.x, out[oo + sub * 2]);
        out[oo + sub * 2 + 1] = fmaf(dn, acc.y, out[oo + sub * 2 + 1]);
        if (sub == 0) {
            out[oo + 32] = fmaf(dn, accx.x, out[oo + 32]);
            out[oo + 33] = fmaf(dn, accx.y, out[oo + 33]);
        }
    }
}

// ---------------------------------------------------------------------------
extern "C" void kernel_launch(void* const* d_in, const int* in_sizes, int n_in,
                              void* d_out, int out_size) {
    const float* x  = (const float*)d_in[0];
    const int*   ei = (const int*)  d_in[1];
    const float* W1 = (const float*)d_in[2];
    const float* b1 = (const float*)d_in[3];
    const float* W2 = (const float*)d_in[4];
    const float* b2 = (const float*)d_in[5];

    int n = in_sizes[0] / DIN;
    int e = in_sizes[1] / 2;
    const int* src = ei;
    const int* dst = ei + e;
    float* out = (float*)d_out;

    int nb = (n + SCAN_BS - 1) / SCAN_BS;
    int e4 = (e + 3) / 4;

    void* degAddr = 0;
    cudaGetSymbolAddress(&degAddr, g_deg);
    cudaMemsetAsync(degAddr, 0, (size_t)n * sizeof(int));

    k_deg_count<<<(e4 + 255) / 256, 256>>>(dst, e);
    k_scan1<<<nb, SCAN_BS>>>(n);
    k_x2h  <<<(n * 16 + 255) / 256, 256>>>(x, n);     // moved up (dep: scan1 only)
    k_scan3<<<nb, SCAN_BS>>>(nb, n);
    k_fill <<<(e4 + 255) / 256, 256>>>(src, dst, e);

    k_aggx <<<(n + 7) / 8, 256>>>(x, n);
    k_fused<<<(n + 127) / 128, 256>>>(W1, b1, W2, b2, out, n);
    k_agg2 <<<(n + 7) / 8, 256>>>(out, n);
}

// round 12
// speedup vs baseline: 1.0924x; 1.0924x over previous
#include <cuda_runtime.h>
#include <cuda_fp16.h>

#define N_MAX 100000
#define E_MAX 1200000
#define DIN   64
#define DHID  64
#define DOUT  34
#define SCAN_BS 512
#define NB_MAX ((N_MAX + SCAN_BS - 1) / SCAN_BS)

// ---- scratch (allocation-free: __device__ globals) ----
__device__ int    g_deg [N_MAX];
__device__ float  g_dinv[N_MAX];
__device__ int    g_off [N_MAX + 1];
__device__ int    g_cur [N_MAX];
__device__ int    g_bsum[NB_MAX];
__device__ int    g_esrc[E_MAX];
__device__ __half g_xh [(size_t)N_MAX * DIN];   // dinv*x, fp16 gather table
__device__ __half g_sh [(size_t)N_MAX * DIN];   // aggregated input, fp16 (GEMM1 A)
__device__ __half g_hwh[(size_t)N_MAX * DOUT];  // dinv*hw, fp16 gather table

// ---------------------------------------------------------------------------
__global__ void k_deg_count(const int* __restrict__ dst, int e) {
    int i0 = (blockIdx.x * blockDim.x + threadIdx.x) * 4;
    if (i0 + 3 < e) {
        int d0 = dst[i0], d1 = dst[i0 + 1], d2 = dst[i0 + 2], d3 = dst[i0 + 3];
        atomicAdd(&g_deg[d0], 1);
        atomicAdd(&g_deg[d1], 1);
        atomicAdd(&g_deg[d2], 1);
        atomicAdd(&g_deg[d3], 1);
    } else {
        for (int i = i0; i < e; i++) atomicAdd(&g_deg[dst[i]], 1);
    }
}

__global__ void k_scan1(int n) {
    __shared__ int sh[SCAN_BS];
    int i = blockIdx.x * SCAN_BS + threadIdx.x;
    int v = (i < n) ? g_deg[i] : 0;
    if (i < n) g_dinv[i] = rsqrtf((float)(v + 1));
    sh[threadIdx.x] = v;
    __syncthreads();
    for (int off = 1; off < SCAN_BS; off <<= 1) {
        int t = (threadIdx.x >= off) ? sh[threadIdx.x - off] : 0;
        __syncthreads();
        sh[threadIdx.x] += t;
        __syncthreads();
    }
    if (i < n) g_off[i] = sh[threadIdx.x] - v;
    if (threadIdx.x == SCAN_BS - 1) g_bsum[blockIdx.x] = sh[threadIdx.x];
}

__global__ void k_scan3(int nb, int n) {
    __shared__ int red[SCAN_BS / 32];
    __shared__ int pref;
    int sb = blockIdx.x, t = threadIdx.x;
    int v = (t < sb) ? g_bsum[t] : 0;
#pragma unroll
    for (int o = 16; o; o >>= 1) v += __shfl_xor_sync(0xffffffffu, v, o);
    if ((t & 31) == 0) red[t >> 5] = v;
    __syncthreads();
    if (t < 32) {
        int vv = (t < SCAN_BS / 32) ? red[t] : 0;
#pragma unroll
        for (int o = 16; o; o >>= 1) vv += __shfl_xor_sync(0xffffffffu, vv, o);
        if (t == 0) pref = vv;
    }
    __syncthreads();
    int prefix = pref;
    int i = sb * SCAN_BS + t;
    if (i < n) {
        int o = g_off[i] + prefix;
        g_off[i] = o;
        g_cur[i] = o;
    }
    if (sb == nb - 1 && t == 0) g_off[n] = prefix + g_bsum[sb];
}

// ---------------------------------------------------------------------------
// Merged: blocks [0, fb) do CSR fill (4 edges/thread, proven);
// blocks [fb, ...) convert x -> fp16 pre-scaled by dinv (proven x2h).
// Fill is latency-bound, x2h is DRAM-bound: co-residency overlaps them.
__global__ void k_fill_x2h(const float* __restrict__ x,
                           const int* __restrict__ src, const int* __restrict__ dst,
                           int n, int e, int fb) {
    if ((int)blockIdx.x < fb) {
        int i0 = (blockIdx.x * blockDim.x + threadIdx.x) * 4;
        if (i0 + 3 < e) {
            int s0 = src[i0], s1 = src[i0 + 1], s2 = src[i0 + 2], s3 = src[i0 + 3];
            int d0 = dst[i0], d1 = dst[i0 + 1], d2 = dst[i0 + 2], d3 = dst[i0 + 3];
            int p0 = atomicAdd(&g_cur[d0], 1);
            int p1 = atomicAdd(&g_cur[d1], 1);
            int p2 = atomicAdd(&g_cur[d2], 1);
            int p3 = atomicAdd(&g_cur[d3], 1);
            g_esrc[p0] = s0; g_esrc[p1] = s1; g_esrc[p2] = s2; g_esrc[p3] = s3;
        } else {
            for (int i = i0; i < e; i++) {
                int pos = atomicAdd(&g_cur[dst[i]], 1);
                g_esrc[pos] = src[i];
            }
        }
    } else {
        int tid = (blockIdx.x - fb) * blockDim.x + threadIdx.x;
        int row = tid >> 4, sub = tid & 15;
        if (row >= n) return;
        float dn = g_dinv[row];
        float4 v = *(const float4*)(x + (size_t)row * DIN + sub * 4);
        __half2 h01 = __floats2half2_rn(v.x * dn, v.y * dn);
        __half2 h23 = __floats2half2_rn(v.z * dn, v.w * dn);
        uint2 raw;
        raw.x = *(unsigned*)&h01;
        raw.y = *(unsigned*)&h23;
        *(uint2*)(g_xh + (size_t)row * DIN + sub * 4) = raw;
    }
}

// ---------------------------------------------------------------------------
// Pre-GEMM aggregation — FROZEN round-9 half-warp uint2 configuration.
__global__ void k_aggx(const float* __restrict__ x, int n) {
    int warp = threadIdx.x >> 5, lane = threadIdx.x & 31;
    int node = blockIdx.x * 8 + warp;
    if (node >= n) return;
    int beg = g_off[node], end = g_off[node + 1];
    int half = lane >> 4, sub = lane & 15;

    float4 acc = make_float4(0.f, 0.f, 0.f, 0.f);
    for (int j = beg; j < end; j += 32) {
        int idx = j + lane;
        int ed = (idx < end) ? g_esrc[idx] : 0;
        int m  = min(32, end - j);
        int mt = (m + 1) >> 1;
        int t  = 0;
        for (; t + 2 <= mt; t += 2) {
            int l0 = 2 * t + half, l1 = l0 + 2;
            int s0 = __shfl_sync(0xffffffffu, ed, l0);
            int s1 = __shfl_sync(0xffffffffu, ed, l1);
            if (l0 < m) {
                uint2 raw = *(const uint2*)(g_xh + (size_t)s0 * DIN + sub * 4);
                float2 f0 = __half22float2(*(__half2*)&raw.x);
                float2 f1 = __half22float2(*(__half2*)&raw.y);
                acc.x += f0.x; acc.y += f0.y; acc.z += f1.x; acc.w += f1.y;
            }
            if (l1 < m) {
                uint2 raw = *(const uint2*)(g_xh + (size_t)s1 * DIN + sub * 4);
                float2 f0 = __half22float2(*(__half2*)&raw.x);
                float2 f1 = __half22float2(*(__half2*)&raw.y);
                acc.x += f0.x; acc.y += f0.y; acc.z += f1.x; acc.w += f1.y;
            }
        }
        for (; t < mt; t++) {
            int l0 = 2 * t + half;
            int s0 = __shfl_sync(0xffffffffu, ed, l0);
            if (l0 < m) {
                uint2 raw = *(const uint2*)(g_xh + (size_t)s0 * DIN + sub * 4);
                float2 f0 = __half22float2(*(__half2*)&raw.x);
                float2 f1 = __half22float2(*(__half2*)&raw.y);
                acc.x += f0.x; acc.y += f0.y; acc.z += f1.x; acc.w += f1.y;
            }
        }
    }
    acc.x += __shfl_xor_sync(0xffffffffu, acc.x, 16);
    acc.y += __shfl_xor_sync(0xffffffffu, acc.y, 16);
    acc.z += __shfl_xor_sync(0xffffffffu, acc.z, 16);
    acc.w += __shfl_xor_sync(0xffffffffu, acc.w, 16);
    if (half == 0) {
        float dn = g_dinv[node];
        float4 xv = *(const float4*)(x + (size_t)node * DIN + sub * 4);
        float sx = fmaf(dn, acc.x, dn * dn * xv.x);
        float sy = fmaf(dn, acc.y, dn * dn * xv.y);
        float sz = fmaf(dn, acc.z, dn * dn * xv.z);
        float sw = fmaf(dn, acc.w, dn * dn * xv.w);
        __half2 h01 = __floats2half2_rn(sx, sy);
        __half2 h23 = __floats2half2_rn(sz, sw);
        uint2 raw;
        raw.x = *(unsigned*)&h01;
        raw.y = *(unsigned*)&h23;
        *(uint2*)(g_sh + (size_t)node * DIN + sub * 4) = raw;
    }
}

// ---------------------------------------------------------------------------
// Tensor-core fused kernel (proven round-9 config, unchanged).
__device__ __forceinline__ void mma16816(float& c0, float& c1, float& c2, float& c3,
                                         unsigned a0, unsigned a1, unsigned a2, unsigned a3,
                                         unsigned b0, unsigned b1) {
    asm volatile(
        "mma.sync.aligned.m16n8k16.row.col.f32.f16.f16.f32 "
        "{%0,%1,%2,%3}, {%4,%5,%6,%7}, {%8,%9}, {%0,%1,%2,%3};"
        : "+f"(c0), "+f"(c1), "+f"(c2), "+f"(c3)
        : "r"(a0), "r"(a1), "r"(a2), "r"(a3), "r"(b0), "r"(b1));
}

__global__ void __launch_bounds__(256) k_fused(
        const float* __restrict__ W1, const float* __restrict__ b1,
        const float* __restrict__ W2, const float* __restrict__ b2,
        float* __restrict__ out, int n) {
    __shared__ __half W1t[64][72];
    __shared__ __half W2t[40][72];
    __shared__ float  b1s[64];
    int tid = threadIdx.x;
    for (int i = tid; i < 64 * 64; i += 256) {
        int k = i >> 6, nn = i & 63;
        W1t[nn][k] = __float2half(W1[k * DHID + nn]);
    }
    for (int i = tid; i < 40 * 64; i += 256) {
        int nn = i / 64, k = i - nn * 64;
        W2t[nn][k] = (nn < DOUT) ? __float2half(W2[k * DOUT + nn]) : __float2half(0.f);
    }
    if (tid < 64) b1s[tid] = b1[tid];
    __syncthreads();

    int warp = tid >> 5, lane = tid & 31;
    int qr = lane >> 2, qc = lane & 3;
    int row0 = blockIdx.x * 128 + warp * 16;
    int r1 = row0 + qr, r2 = r1 + 8;
    bool v1 = r1 < n, v2 = r2 < n;

    const unsigned* gs32 = (const unsigned*)g_sh;

    float c[8][4];
#pragma unroll
    for (int nt = 0; nt < 8; nt++)
        c[nt][0] = c[nt][1] = c[nt][2] = c[nt][3] = 0.f;

#pragma unroll
    for (int kt = 0; kt < 4; kt++) {
        int col = kt * 16 + qc * 2;
        unsigned a0 = 0, a1 = 0, a2 = 0, a3 = 0;
        if (v1) { a0 = gs32[(r1 * DIN + col) >> 1]; a2 = gs32[(r1 * DIN + col + 8) >> 1]; }
        if (v2) { a1 = gs32[(r2 * DIN + col) >> 1]; a3 = gs32[(r2 * DIN + col + 8) >> 1]; }
#pragma unroll
        for (int nt = 0; nt < 8; nt++) {
            unsigned b0 = *(const unsigned*)&W1t[nt * 8 + qr][col];
            unsigned b1r = *(const unsigned*)&W1t[nt * 8 + qr][col + 8];
            mma16816(c[nt][0], c[nt][1], c[nt][2], c[nt][3], a0, a1, a2, a3, b0, b1r);
        }
    }

    float m1 = 0.f, m2 = 0.f;
#pragma unroll
    for (int nt = 0; nt < 8; nt++) {
        float2 bb = *(const float2*)&b1s[nt * 8 + qc * 2];
        c[nt][0] = fmaxf(c[nt][0] + bb.x, 0.f);
        c[nt][1] = fmaxf(c[nt][1] + bb.y, 0.f);
        c[nt][2] = fmaxf(c[nt][2] + bb.x, 0.f);
        c[nt][3] = fmaxf(c[nt][3] + bb.y, 0.f);
        m1 = fmaxf(m1, fmaxf(c[nt][0], c[nt][1]));
        m2 = fmaxf(m2, fmaxf(c[nt][2], c[nt][3]));
    }
    m1 = fmaxf(m1, __shfl_xor_sync(0xffffffffu, m1, 1));
    m1 = fmaxf(m1, __shfl_xor_sync(0xffffffffu, m1, 2));
    m2 = fmaxf(m2, __shfl_xor_sync(0xffffffffu, m2, 1));
    m2 = fmaxf(m2, __shfl_xor_sync(0xffffffffu, m2, 2));
    float s1 = 0.f, s2 = 0.f;
#pragma unroll
    for (int nt = 0; nt < 8; nt++) {
        c[nt][0] = __expf(c[nt][0] - m1);
        c[nt][1] = __expf(c[nt][1] - m1);
        c[nt][2] = __expf(c[nt][2] - m2);
        c[nt][3] = __expf(c[nt][3] - m2);
        s1 += c[nt][0] + c[nt][1];
        s2 += c[nt][2] + c[nt][3];
    }
    s1 += __shfl_xor_sync(0xffffffffu, s1, 1);
    s1 += __shfl_xor_sync(0xffffffffu, s1, 2);
    s2 += __shfl_xor_sync(0xffffffffu, s2, 1);
    s2 += __shfl_xor_sync(0xffffffffu, s2, 2);
    float i1 = 1.0f / s1, i2 = 1.0f / s2;

    unsigned pa[4][4];
#pragma unroll
    for (int kt = 0; kt < 4; kt++) {
        __half2 h;
        h = __floats2half2_rn(c[2 * kt][0] * i1, c[2 * kt][1] * i1);         pa[kt][0] = *(unsigned*)&h;
        h = __floats2half2_rn(c[2 * kt][2] * i2, c[2 * kt][3] * i2);         pa[kt][1] = *(unsigned*)&h;
        h = __floats2half2_rn(c[2 * kt + 1][0] * i1, c[2 * kt + 1][1] * i1); pa[kt][2] = *(unsigned*)&h;
        h = __floats2half2_rn(c[2 * kt + 1][2] * i2, c[2 * kt + 1][3] * i2); pa[kt][3] = *(unsigned*)&h;
    }

    float dn1 = v1 ? g_dinv[r1] : 0.f;
    float dn2 = v2 ? g_dinv[r2] : 0.f;

#pragma unroll
    for (int nt = 0; nt < 5; nt++) {
        float d0 = 0.f, d1 = 0.f, d2 = 0.f, d3 = 0.f;
#pragma unroll
        for (int kt = 0; kt < 4; kt++) {
            int kk = kt * 16 + qc * 2;
            unsigned b0 = *(const unsigned*)&W2t[nt * 8 + qr][kk];
            unsigned b1r = *(const unsigned*)&W2t[nt * 8 + qr][kk + 8];
            mma16816(d0, d1, d2, d3, pa[kt][0], pa[kt][1], pa[kt][2], pa[kt][3], b0, b1r);
        }
        int col = nt * 8 + qc * 2;
        if (col + 1 < DOUT) {
            float2 bb = *(const float2*)&b2[col];
            if (v1) {
                float2 o;
                o.x = fmaf(dn1 * dn1, d0, bb.x);
                o.y = fmaf(dn1 * dn1, d1, bb.y);
                *(float2*)&out[(size_t)r1 * DOUT + col] = o;
                __half2 hh = __floats2half2_rn(dn1 * d0, dn1 * d1);
                *(__half2*)&g_hwh[(size_t)r1 * DOUT + col] = hh;
            }
            if (v2) {
                float2 o;
                o.x = fmaf(dn2 * dn2, d2, bb.x);
                o.y = fmaf(dn2 * dn2, d3, bb.y);
                *(float2*)&out[(size_t)r2 * DOUT + col] = o;
                __half2 hh = __floats2half2_rn(dn2 * d2, dn2 * d3);
                *(__half2*)&g_hwh[(size_t)r2 * DOUT + col] = hh;
            }
        }
    }
}

// ---------------------------------------------------------------------------
// Layer-2 aggregation — FROZEN proven config.
__global__ void k_agg2(float* __restrict__ out, int n) {
    int warp = threadIdx.x >> 5, lane = threadIdx.x & 31;
    int node = blockIdx.x * 8 + warp;
    if (node >= n) return;
    int beg = g_off[node], end = g_off[node + 1];
    int half = lane >> 4, sub = lane & 15;

    float2 acc  = make_float2(0.f, 0.f);
    float2 accx = make_float2(0.f, 0.f);
    for (int j = beg; j < end; j += 32) {
        int idx = j + lane;
        int ed = (idx < end) ? g_esrc[idx] : 0;
        int m  = min(32, end - j);
        int mt = (m + 1) >> 1;
        int t  = 0;
        for (; t + 2 <= mt; t += 2) {
            int l0 = 2 * t + half, l1 = l0 + 2;
            int s0 = __shfl_sync(0xffffffffu, ed, l0);
            int s1 = __shfl_sync(0xffffffffu, ed, l1);
            if (l0 < m) {
                const __half* hp = g_hwh + (size_t)s0 * DOUT;
                float2 v = __half22float2(*(const __half2*)(hp + sub * 2));
                acc.x += v.x; acc.y += v.y;
                if (sub == 0) {
                    float2 u = __half22float2(*(const __half2*)(hp + 32));
                    accx.x += u.x; accx.y += u.y;
                }
            }
            if (l1 < m) {
                const __half* hp = g_hwh + (size_t)s1 * DOUT;
                float2 v = __half22float2(*(const __half2*)(hp + sub * 2));
                acc.x += v.x; acc.y += v.y;
                if (sub == 0) {
                    float2 u = __half22float2(*(const __half2*)(hp + 32));
                    accx.x += u.x; accx.y += u.y;
                }
            }
        }
        for (; t < mt; t++) {
            int l0 = 2 * t + half;
            int s0 = __shfl_sync(0xffffffffu, ed, l0);
            if (l0 < m) {
                const __half* hp = g_hwh + (size_t)s0 * DOUT;
                float2 v = __half22float2(*(const __half2*)(hp + sub * 2));
                acc.x += v.x; acc.y += v.y;
                if (sub == 0) {
                    float2 u = __half22float2(*(const __half2*)(hp + 32));
                    accx.x += u.x; accx.y += u.y;
                }
            }
        }
    }
    acc.x  += __shfl_xor_sync(0xffffffffu, acc.x,  16);
    acc.y  += __shfl_xor_sync(0xffffffffu, acc.y,  16);
    accx.x += __shfl_xor_sync(0xffffffffu, accx.x, 16);
    accx.y += __shfl_xor_sync(0xffffffffu, accx.y, 16);
    if (half == 0) {
        float dn = g_dinv[node];
        size_t oo = (size_t)node * DOUT;
        out[oo + sub * 2]     = fmaf(dn, acc.x, out[oo + sub * 2]);
        out[oo + sub * 2 + 1] = fmaf(dn, acc.y, out[oo + sub * 2 + 1]);
        if (sub == 0) {
            out[oo + 32] = fmaf(dn, accx.x, out[oo + 32]);
            out[oo + 33] = fmaf(dn, accx.y, out[oo + 33]);
        }
    }
}

// ---------------------------------------------------------------------------
extern "C" void kernel_launch(void* const* d_in, const int* in_sizes, int n_in,
                              void* d_out, int out_size) {
    const float* x  = (const float*)d_in[0];
    const int*   ei = (const int*)  d_in[1];
    const float* W1 = (const float*)d_in[2];
    const float* b1 = (const float*)d_in[3];
    const float* W2 = (const float*)d_in[4];
    const float* b2 = (const float*)d_in[5];

    int n = in_sizes[0] / DIN;
    int e = in_sizes[1] / 2;
    const int* src = ei;
    const int* dst = ei + e;
    float* out = (float*)d_out;

    int nb = (n + SCAN_BS - 1) / SCAN_BS;
    int e4 = (e + 3) / 4;
    int fb = (e4 + 255) / 256;           // fill blocks
    int xb = (n * 16 + 255) / 256;       // x2h blocks

    void* degAddr = 0;
    cudaGetSymbolAddress(&degAddr, g_deg);
    cudaMemsetAsync(degAddr, 0, (size_t)n * sizeof(int));

    k_deg_count<<<(e4 + 255) / 256, 256>>>(dst, e);
    k_scan1<<<nb, SCAN_BS>>>(n);
    k_scan3<<<nb, SCAN_BS>>>(nb, n);
    k_fill_x2h<<<fb + xb, 256>>>(x, src, dst, n, e, fb);

    k_aggx <<<(n + 7) / 8, 256>>>(x, n);
    k_fused<<<(n + 127) / 128, 256>>>(W1, b1, W2, b2, out, n);
    k_agg2 <<<(n + 7) / 8, 256>>>(out, n);
}